// round 16
// baseline (speedup 1.0000x reference)
#include <cuda_runtime.h>
#include <cuda_bf16.h>

#define NN    50000
#define NBLK  782         // ceil(50000/64)
#define HSZ   132         // fp32 activation smem stride (out kernel)
#define WFT   136         // fp32 full-weight smem stride (out kernel)
#define BST   144         // bf16 smem stride: 288B -> conflict-free LDS.64 per phase
#define HRB   (BST*2)     // h row bytes
#define HG4   (16*HRB)    // one h buffer (per group, per parity): 4608 B

// ---------------- device scratch (statics; no runtime allocs) ----------------
__device__ __nv_bfloat16 g_P [(size_t)NN * 512];  // projected inputs + bias (bf16)
__device__ float g_H  [(size_t)NN * 128];         // layer-1 output (post-ReLU)
__device__ float g_Hn [(size_t)NN * 128];         // LSTM final hidden per node
__device__ __nv_bfloat16 g_WihB[512 * 128];       // bf16, k16-permuted (proj)
__device__ __nv_bfloat16 g_WhhB[512 * 128];       // bf16, k16-permuted (lstm)
__device__ float g_Wself [128 * 128];             // tf32, k8-permuted (out)
__device__ float g_Wneigh[128 * 128];
__device__ float g_bsum[512];
__device__ float g_bout[128];

// ---------------- helpers ----------------
__device__ __forceinline__ unsigned tf32u(float f) {
    unsigned u; asm("cvt.rna.tf32.f32 %0, %1;" : "=r"(u) : "f"(f)); return u;
}
__device__ __forceinline__ float tf32f(float f) { return __uint_as_float(tf32u(f)); }
__device__ __forceinline__ float sigf(float x)  { return __fdividef(1.f, 1.f + __expf(-x)); }
__device__ __forceinline__ float tanha(float x) {
    float y; asm("tanh.approx.f32 %0, %1;" : "=f"(y) : "f"(x)); return y;
}
__device__ __forceinline__ float siga(float x) { return fmaf(0.5f, tanha(0.5f * x), 0.5f); }

__device__ __forceinline__ void mma8(float* c, unsigned a0, unsigned a1, unsigned a2,
                                     unsigned a3, unsigned b0, unsigned b1) {
    asm volatile("mma.sync.aligned.m16n8k8.row.col.f32.tf32.tf32.f32 "
                 "{%0,%1,%2,%3}, {%4,%5,%6,%7}, {%8,%9}, {%0,%1,%2,%3};"
                 : "+f"(c[0]), "+f"(c[1]), "+f"(c[2]), "+f"(c[3])
                 : "r"(a0), "r"(a1), "r"(a2), "r"(a3), "r"(b0), "r"(b1));
}
__device__ __forceinline__ void mma16(float* c, unsigned a0, unsigned a1, unsigned a2,
                                      unsigned a3, unsigned b0, unsigned b1) {
    asm volatile("mma.sync.aligned.m16n8k16.row.col.f32.bf16.bf16.f32 "
                 "{%0,%1,%2,%3}, {%4,%5,%6,%7}, {%8,%9}, {%0,%1,%2,%3};"
                 : "+f"(c[0]), "+f"(c[1]), "+f"(c[2]), "+f"(c[3])
                 : "r"(a0), "r"(a1), "r"(a2), "r"(a3), "r"(b0), "r"(b1));
}
__device__ __forceinline__ unsigned packbf2(float hi, float lo) {
    unsigned r; asm("cvt.rn.bf16x2.f32 %0, %1, %2;" : "=r"(r) : "f"(hi), "f"(lo)); return r;
}
__device__ __forceinline__ float lo2f(unsigned u) { return __uint_as_float(u << 16); }
__device__ __forceinline__ float hi2f(unsigned u) { return __uint_as_float(u & 0xFFFF0000u); }
__device__ __forceinline__ void cpa16(void* dst, const void* src) {
    unsigned d = (unsigned)__cvta_generic_to_shared(dst);
    asm volatile("cp.async.cg.shared.global [%0], [%1], 16;" :: "r"(d), "l"(src));
}
__device__ __forceinline__ void cpcommit() { asm volatile("cp.async.commit_group;"); }
__device__ __forceinline__ int perm16(int k) {
    return (k & ~15) | ((k & 6) << 1) | ((k & 8) >> 2) | (k & 1);
}

// ---------------- prep ----------------
__global__ void prep_kernel(const float* __restrict__ wih, const float* __restrict__ whh,
                            const float* __restrict__ bih, const float* __restrict__ bhh,
                            const float* __restrict__ wself, const float* __restrict__ wneigh,
                            const float* __restrict__ bo, int hout) {
    int i = blockIdx.x * 256 + threadIdx.x;
    if (i < 512 * 128) {
        int n = i >> 7, k = i & 127;
        g_WihB[n * 128 + perm16(k)] = __float2bfloat16(wih[i]);
        g_WhhB[n * 128 + perm16(k)] = __float2bfloat16(whh[i]);
    }
    if (i < hout * 128) {
        int n = i >> 7, k = i & 127;
        int kp = (k & ~7) | ((k & 3) << 1) | ((k >> 2) & 1);   // tf32 k8 perm
        g_Wself[n * 128 + kp]  = tf32f(wself[i]);
        g_Wneigh[n * 128 + kp] = tf32f(wneigh[i]);
    }
    if (i < 512)  g_bsum[i] = bih[i] + bhh[i];
    if (i < 128 && i < hout) g_bout[i] = bo[i];
}

// ---------------- proj: P = bf16(x @ Wih^T + bsum), single k-pass (R12) ----------------
__global__ void __launch_bounds__(512, 1) proj_kernel(const float* __restrict__ xext, int sel) {
    extern __shared__ char smraw[];
    __nv_bfloat16* wsm = (__nv_bfloat16*)smraw;               // 512 x BST
    __nv_bfloat16* xs  = wsm + 512 * BST;                     // 64 x BST
    const float* x = sel ? g_H : xext;

    int tid = threadIdx.x, lane = tid & 31, warp = tid >> 5;
    int gid = lane >> 2, tig = lane & 3;
    int base = blockIdx.x * 64;
    int cb = warp * 8 + 2 * tig;

#pragma unroll
    for (int i = 0; i < 16; i++) {
        int idx = tid + i * 512;
        int n = idx >> 4, c = idx & 15;
        cpa16(wsm + n * BST + c * 8, g_WihB + n * 128 + c * 8);
    }
    cpcommit();
    {
        int r = tid >> 3, c0 = (tid & 7) * 16;
        const float* xr = x + (size_t)(base + r) * 128;
        bool v = base + r < NN;
#pragma unroll
        for (int p = 0; p < 8; p++) {
            int col = c0 + 2 * p;
            float2 vv = v ? *(const float2*)&xr[col] : make_float2(0.f, 0.f);
            *(unsigned*)((char*)xs + r * HRB + perm16(col) * 2) = packbf2(vv.y, vv.x);
        }
    }
    asm volatile("cp.async.wait_group 0;");
    __syncthreads();

    float acc[4][4][4];
#pragma unroll
    for (int g = 0; g < 4; g++)
#pragma unroll
        for (int m = 0; m < 4; m++)
#pragma unroll
            for (int s = 0; s < 4; s++) acc[g][m][s] = 0.f;

    const char* xsb = (const char*)xs;
    const char* wb  = (const char*)wsm;
#pragma unroll
    for (int kc = 0; kc < 8; kc++) {
        uint2 va[4], vb[4];
#pragma unroll
        for (int m = 0; m < 4; m++) {
            va[m] = *(const uint2*)(xsb + (m * 16 + gid) * HRB + kc * 32 + tig * 8);
            vb[m] = *(const uint2*)(xsb + (m * 16 + 8 + gid) * HRB + kc * 32 + tig * 8);
        }
#pragma unroll
        for (int g = 0; g < 4; g++) {
            uint2 b = *(const uint2*)(wb + (g * 128 + warp * 8 + gid) * HRB
                                      + kc * 32 + tig * 8);
#pragma unroll
            for (int m = 0; m < 4; m++)
                mma16(acc[g][m], va[m].x, vb[m].x, va[m].y, vb[m].y, b.x, b.y);
        }
    }
#pragma unroll
    for (int m = 0; m < 4; m++) {
        int rA = base + m * 16 + gid, rB = rA + 8;
        bool vA = rA < NN, vB = rB < NN;
        size_t nA = (size_t)rA * 512, nB = (size_t)rB * 512;
#pragma unroll
        for (int g = 0; g < 4; g++) {
            int col = g * 128 + cb;
            float2 bb = *(const float2*)&g_bsum[col];
            if (vA) *(unsigned*)&g_P[nA + col] =
                        packbf2(acc[g][m][1] + bb.y, acc[g][m][0] + bb.x);
            if (vB) *(unsigned*)&g_P[nB + col] =
                        packbf2(acc[g][m][3] + bb.y, acc[g][m][2] + bb.x);
        }
    }
}

// ------- lstm: four independent 128-thread groups (named barriers), t=0 GEMM peeled -------
__global__ void __launch_bounds__(512, 1) lstm_kernel(const int* __restrict__ nbr) {
    extern __shared__ char smraw[];
    __nv_bfloat16* wsm = (__nv_bfloat16*)smraw;       // 512 x BST
    char* hall = smraw + 512 * BST * 2;               // 4 groups x 2 parity x 16 x HRB
    int*  snbr = (int*)(hall + 8 * HG4);              // 64 x 16

    int tid = threadIdx.x, lane = tid & 31, warp = tid >> 5;
    int grp = warp >> 2, gw = warp & 3;
    int gid = lane >> 2, tig = lane & 3;
    int base0 = blockIdx.x * 64;
    int gbase = base0 + grp * 16;

    // stage W_hh once (all 512 threads)
#pragma unroll
    for (int i = 0; i < 16; i++) {
        int idx = tid + i * 512;
        int n = idx >> 4, c = idx & 15;
        cpa16(wsm + n * BST + c * 8, g_WhhB + n * 128 + c * 8);
    }
    cpcommit();
#pragma unroll
    for (int i = 0; i < 2; i++) {
        int idx = tid + i * 512;
        int r = idx >> 4;
        snbr[idx] = (base0 + r < NN) ? nbr[(size_t)(base0 + r) * 16 + (idx & 15)] : 0;
    }
    asm volatile("cp.async.wait_group 0;");
    __syncthreads();

    char* hbuf = hall + grp * 2 * HG4;
    const char* wbase = (const char*)wsm;
    int cb = gw * 32 + 2 * tig;             // per-gate column base; tt adds +8
    int bid = grp + 1;                      // named barrier id (1..4)

    float acc[4][4][4];                     // [gate][tt][frag]
    float cst[4][4];                        // [tt][frag]
#pragma unroll
    for (int tt = 0; tt < 4; tt++)
#pragma unroll
        for (int z = 0; z < 4; z++) cst[tt][z] = 0.f;

    auto gatherP = [&](int t) {
        int r0 = grp * 16 + gid;
        const __nv_bfloat16* PA = g_P + (size_t)snbr[r0 * 16 + t] * 512;
        const __nv_bfloat16* PB = g_P + (size_t)snbr[(r0 + 8) * 16 + t] * 512;
#pragma unroll
        for (int g = 0; g < 4; g++)
#pragma unroll
            for (int tt = 0; tt < 4; tt++) {
                unsigned ua = *(const unsigned*)(PA + g * 128 + cb + tt * 8);
                unsigned ub = *(const unsigned*)(PB + g * 128 + cb + tt * 8);
                acc[g][tt][0] = lo2f(ua); acc[g][tt][1] = hi2f(ua);
                acc[g][tt][2] = lo2f(ub); acc[g][tt][3] = hi2f(ub);
            }
    };

    auto cell = [&](int t, char* hn) {
#pragma unroll
        for (int tt = 0; tt < 4; tt++) {
            float hv[4];
#pragma unroll
            for (int z = 0; z < 4; z++) {
                float iv = siga(acc[0][tt][z]);
                float fv = siga(acc[1][tt][z]);
                float gv = tanha(acc[2][tt][z]);
                float ov = siga(acc[3][tt][z]);
                float c = fv * cst[tt][z] + iv * gv;
                cst[tt][z] = c;
                hv[z] = ov * tanha(c);
            }
            int u0 = cb + tt * 8;
            if (t < 15) {
                int phys = (u0 & ~15) | ((u0 & 6) << 1) | ((u0 & 8) >> 2);
                *(unsigned*)(hn + gid * HRB + phys * 2)       = packbf2(hv[1], hv[0]);
                *(unsigned*)(hn + (8 + gid) * HRB + phys * 2) = packbf2(hv[3], hv[2]);
            } else {
                int rA = gbase + gid, rB = rA + 8;
                if (rA < NN) *(float2*)&g_Hn[(size_t)rA * 128 + u0] = make_float2(hv[0], hv[1]);
                if (rB < NN) *(float2*)&g_Hn[(size_t)rB * 128 + u0] = make_float2(hv[2], hv[3]);
            }
        }
    };

    // t = 0 peeled: h0 = 0, gates = P only -> no GEMM, no h-buffer zeroing
    gatherP(0);
    cell(0, hbuf + 1 * HG4);
    gatherP(1);
    asm volatile("bar.sync %0, 128;" :: "r"(bid) : "memory");

    for (int t = 1; t < 16; t++) {
        const char* hc = hbuf + (t & 1) * HG4;
        char*       hn = hbuf + ((t + 1) & 1) * HG4;

        // acc += h @ Whh^T  (bf16 m16n8k16; group covers 16 rows x 512 cols)
#pragma unroll
        for (int kc = 0; kc < 8; kc++) {
            uint2 va = *(const uint2*)(hc + gid * HRB + kc * 32 + tig * 8);
            uint2 vb = *(const uint2*)(hc + (8 + gid) * HRB + kc * 32 + tig * 8);
#pragma unroll
            for (int g = 0; g < 4; g++)
#pragma unroll
                for (int tt = 0; tt < 4; tt++) {
                    uint2 b = *(const uint2*)(wbase + (g * 128 + gw * 32 + tt * 8 + gid) * HRB
                                              + kc * 32 + tig * 8);
                    mma16(acc[g][tt], va.x, vb.x, va.y, vb.y, b.x, b.y);
                }
        }

        cell(t, hn);
        if (t < 15) gatherP(t + 1);
        asm volatile("bar.sync %0, 128;" :: "r"(bid) : "memory");   // per-group step barrier
    }
}

// ---------------- out: o = x@Wself^T + hN@Wneigh^T + b  (+ ReLU / sigmoid) ----------------
template<int HOUT, int ACT>
__global__ void __launch_bounds__(512, 1) out_kernel(const float* __restrict__ xext, int sel,
                                                     float* __restrict__ oext, int osel) {
    extern __shared__ float sm[];
    float* xs = sm;
    float* h2 = xs + 64 * HSZ;
    float* ws = h2 + 64 * HSZ;
    float* wn = ws + HOUT * WFT;
    const float* x = sel ? g_H : xext;
    float* o = osel ? oext : g_H;
    int tid = threadIdx.x, lane = tid & 31, warp = tid >> 5;
    int wr = warp >> 2, cg = warp & 3, gid = lane >> 2, tig = lane & 3;
    int base = blockIdx.x * 64;
    int rowA = wr * 16 + gid, rowB = rowA + 8;
    bool vA = base + rowA < NN, vB = base + rowB < NN;

#pragma unroll
    for (int i = 0; i < 4; i++) {
        int idx = tid + i * 512;
        int r = idx >> 5, c = idx & 31;
        if (base + r < NN) {
            cpa16(xs + r * HSZ + c * 4, x    + (size_t)(base + r) * 128 + c * 4);
            cpa16(h2 + r * HSZ + c * 4, g_Hn + (size_t)(base + r) * 128 + c * 4);
        }
    }
#pragma unroll
    for (int i = 0; i < HOUT * 32 / 512; i++) {
        int idx = tid + i * 512;
        int n = idx >> 5, c = idx & 31;
        cpa16(ws + n * WFT + c * 4, g_Wself  + n * 128 + c * 4);
        cpa16(wn + n * WFT + c * 4, g_Wneigh + n * 128 + c * 4);
    }
    cpcommit();
    asm volatile("cp.async.wait_group 0;");
    __syncthreads();

    constexpr int T = HOUT / 32;
    float acc[T][4];
#pragma unroll
    for (int tt = 0; tt < T; tt++)
#pragma unroll
        for (int s = 0; s < 4; s++) acc[tt][s] = 0.f;

#pragma unroll
    for (int p = 0; p < 2; p++) {
        const float* As = p ? h2 : xs;
        const float* W  = p ? wn : ws;
#pragma unroll
        for (int kc = 0; kc < 16; kc++) {
            int kk = kc * 8;
            unsigned a0 = tf32u(As[rowA * HSZ + kk + tig]);
            unsigned a1 = tf32u(As[rowB * HSZ + kk + tig]);
            unsigned a2 = tf32u(As[rowA * HSZ + kk + tig + 4]);
            unsigned a3 = tf32u(As[rowB * HSZ + kk + tig + 4]);
#pragma unroll
            for (int tt = 0; tt < T; tt++) {
                float2 b = *(const float2*)&W[(cg * (HOUT / 4) + tt * 8 + gid) * WFT
                                              + kk + 2 * tig];
                mma8(acc[tt], a0, a1, a2, a3, __float_as_uint(b.x), __float_as_uint(b.y));
            }
        }
    }
#pragma unroll
    for (int tt = 0; tt < T; tt++)
#pragma unroll
        for (int s = 0; s < 4; s++) {
            int u = cg * (HOUT / 4) + tt * 8 + 2 * tig + (s & 1);
            float v = acc[tt][s] + g_bout[u];
            v = ACT ? sigf(v) : fmaxf(v, 0.f);
            int row = (s < 2) ? rowA : rowB;
            bool vv = (s < 2) ? vA : vB;
            if (vv) o[(size_t)(base + row) * HOUT + u] = v;
        }
}

// ---------------- launch ----------------
extern "C" void kernel_launch(void* const* d_in, const int* in_sizes, int n_in,
                              void* d_out, int out_size) {
    const float* feats = (const float*)d_in[0];
    const int*   nbr   = (const int*)d_in[1];

    const int PSM  = (512 * BST + 64 * BST) * 2;                 // 165888
    const int LSM  = 512 * BST * 2 + 8 * HG4 + 64 * 16 * 4;      // 188416
    const int OSM1 = (2 * 64 * HSZ + 2 * 128 * WFT) * 4;         // 206848
    const int OSM2 = (2 * 64 * HSZ + 2 * 64 * WFT) * 4;          // 137216
    cudaFuncSetAttribute(proj_kernel,       cudaFuncAttributeMaxDynamicSharedMemorySize, PSM);
    cudaFuncSetAttribute(lstm_kernel,       cudaFuncAttributeMaxDynamicSharedMemorySize, LSM);
    cudaFuncSetAttribute(out_kernel<128,0>, cudaFuncAttributeMaxDynamicSharedMemorySize, OSM1);
    cudaFuncSetAttribute(out_kernel<64,1>,  cudaFuncAttributeMaxDynamicSharedMemorySize, OSM2);

    dim3 g(NBLK), b(512);

    // layer 1
    prep_kernel<<<256, 256>>>((const float*)d_in[2], (const float*)d_in[3],
                              (const float*)d_in[4], (const float*)d_in[5],
                              (const float*)d_in[6], (const float*)d_in[7],
                              (const float*)d_in[8], 128);
    proj_kernel<<<g, b, PSM>>>(feats, 0);
    lstm_kernel<<<g, b, LSM>>>(nbr);
    out_kernel<128, 0><<<g, b, OSM1>>>(feats, 0, nullptr, 0);

    // layer 2
    prep_kernel<<<256, 256>>>((const float*)d_in[9],  (const float*)d_in[10],
                              (const float*)d_in[11], (const float*)d_in[12],
                              (const float*)d_in[13], (const float*)d_in[14],
                              (const float*)d_in[15], 64);
    proj_kernel<<<g, b, PSM>>>(nullptr, 1);
    lstm_kernel<<<g, b, LSM>>>(nbr);
    out_kernel<64, 1><<<g, b, OSM2>>>(nullptr, 1, (float*)d_out, 1);
}

// round 17
// speedup vs baseline: 1.0495x; 1.0495x over previous
#include <cuda_runtime.h>
#include <cuda_bf16.h>

#define NN    50000
#define NBLK  782         // ceil(50000/64)
#define HSZ   132         // fp32 activation smem stride (out kernel)
#define WFT   136         // fp32 full-weight smem stride (out kernel)
#define BST   144         // bf16 smem stride: 288B -> conflict-free LDS.64 per phase
#define HRB   (BST*2)     // h row bytes
#define HG    (32*HRB)    // one h buffer (per group, per parity): 9216 B

// ---------------- device scratch (statics; no runtime allocs) ----------------
__device__ __nv_bfloat16 g_P [(size_t)NN * 512];  // projected inputs + bias (bf16)
__device__ float g_H  [(size_t)NN * 128];         // layer-1 output (post-ReLU)
__device__ float g_Hn [(size_t)NN * 128];         // LSTM final hidden per node
__device__ __nv_bfloat16 g_WihB[512 * 128];       // bf16, k16-permuted (proj)
__device__ __nv_bfloat16 g_WhhB[512 * 128];       // bf16, k16-permuted (lstm)
__device__ float g_Wself [128 * 128];             // tf32, k8-permuted (out)
__device__ float g_Wneigh[128 * 128];
__device__ float g_bsum[512];
__device__ float g_bout[128];

// ---------------- helpers ----------------
__device__ __forceinline__ unsigned tf32u(float f) {
    unsigned u; asm("cvt.rna.tf32.f32 %0, %1;" : "=r"(u) : "f"(f)); return u;
}
__device__ __forceinline__ float tf32f(float f) { return __uint_as_float(tf32u(f)); }
__device__ __forceinline__ float sigf(float x)  { return __fdividef(1.f, 1.f + __expf(-x)); }
__device__ __forceinline__ float tanha(float x) {
    float y; asm("tanh.approx.f32 %0, %1;" : "=f"(y) : "f"(x)); return y;
}
__device__ __forceinline__ float siga(float x) { return fmaf(0.5f, tanha(0.5f * x), 0.5f); }

__device__ __forceinline__ void mma8(float* c, unsigned a0, unsigned a1, unsigned a2,
                                     unsigned a3, unsigned b0, unsigned b1) {
    asm volatile("mma.sync.aligned.m16n8k8.row.col.f32.tf32.tf32.f32 "
                 "{%0,%1,%2,%3}, {%4,%5,%6,%7}, {%8,%9}, {%0,%1,%2,%3};"
                 : "+f"(c[0]), "+f"(c[1]), "+f"(c[2]), "+f"(c[3])
                 : "r"(a0), "r"(a1), "r"(a2), "r"(a3), "r"(b0), "r"(b1));
}
__device__ __forceinline__ void mma16(float* c, unsigned a0, unsigned a1, unsigned a2,
                                      unsigned a3, unsigned b0, unsigned b1) {
    asm volatile("mma.sync.aligned.m16n8k16.row.col.f32.bf16.bf16.f32 "
                 "{%0,%1,%2,%3}, {%4,%5,%6,%7}, {%8,%9}, {%0,%1,%2,%3};"
                 : "+f"(c[0]), "+f"(c[1]), "+f"(c[2]), "+f"(c[3])
                 : "r"(a0), "r"(a1), "r"(a2), "r"(a3), "r"(b0), "r"(b1));
}
__device__ __forceinline__ unsigned packbf2(float hi, float lo) {
    unsigned r; asm("cvt.rn.bf16x2.f32 %0, %1, %2;" : "=r"(r) : "f"(hi), "f"(lo)); return r;
}
__device__ __forceinline__ float lo2f(unsigned u) { return __uint_as_float(u << 16); }
__device__ __forceinline__ float hi2f(unsigned u) { return __uint_as_float(u & 0xFFFF0000u); }
__device__ __forceinline__ void cpa16(void* dst, const void* src) {
    unsigned d = (unsigned)__cvta_generic_to_shared(dst);
    asm volatile("cp.async.cg.shared.global [%0], [%1], 16;" :: "r"(d), "l"(src));
}
__device__ __forceinline__ void cpcommit() { asm volatile("cp.async.commit_group;"); }
__device__ __forceinline__ int perm16(int k) {
    return (k & ~15) | ((k & 6) << 1) | ((k & 8) >> 2) | (k & 1);
}

// ---------------- prep ----------------
__global__ void prep_kernel(const float* __restrict__ wih, const float* __restrict__ whh,
                            const float* __restrict__ bih, const float* __restrict__ bhh,
                            const float* __restrict__ wself, const float* __restrict__ wneigh,
                            const float* __restrict__ bo, int hout) {
    int i = blockIdx.x * 256 + threadIdx.x;
    if (i < 512 * 128) {
        int n = i >> 7, k = i & 127;
        g_WihB[n * 128 + perm16(k)] = __float2bfloat16(wih[i]);
        g_WhhB[n * 128 + perm16(k)] = __float2bfloat16(whh[i]);
    }
    if (i < hout * 128) {
        int n = i >> 7, k = i & 127;
        int kp = (k & ~7) | ((k & 3) << 1) | ((k >> 2) & 1);   // tf32 k8 perm
        g_Wself[n * 128 + kp]  = tf32f(wself[i]);
        g_Wneigh[n * 128 + kp] = tf32f(wneigh[i]);
    }
    if (i < 512)  g_bsum[i] = bih[i] + bhh[i];
    if (i < 128 && i < hout) g_bout[i] = bo[i];
}

// ---------------- proj: P = bf16(x @ Wih^T + bsum), single k-pass (R12) ----------------
__global__ void __launch_bounds__(512, 1) proj_kernel(const float* __restrict__ xext, int sel) {
    extern __shared__ char smraw[];
    __nv_bfloat16* wsm = (__nv_bfloat16*)smraw;               // 512 x BST
    __nv_bfloat16* xs  = wsm + 512 * BST;                     // 64 x BST
    const float* x = sel ? g_H : xext;

    int tid = threadIdx.x, lane = tid & 31, warp = tid >> 5;
    int gid = lane >> 2, tig = lane & 3;
    int base = blockIdx.x * 64;
    int cb = warp * 8 + 2 * tig;

#pragma unroll
    for (int i = 0; i < 16; i++) {
        int idx = tid + i * 512;
        int n = idx >> 4, c = idx & 15;
        cpa16(wsm + n * BST + c * 8, g_WihB + n * 128 + c * 8);
    }
    cpcommit();
    {
        int r = tid >> 3, c0 = (tid & 7) * 16;
        const float* xr = x + (size_t)(base + r) * 128;
        bool v = base + r < NN;
#pragma unroll
        for (int p = 0; p < 8; p++) {
            int col = c0 + 2 * p;
            float2 vv = v ? *(const float2*)&xr[col] : make_float2(0.f, 0.f);
            *(unsigned*)((char*)xs + r * HRB + perm16(col) * 2) = packbf2(vv.y, vv.x);
        }
    }
    asm volatile("cp.async.wait_group 0;");
    __syncthreads();

    float acc[4][4][4];
#pragma unroll
    for (int g = 0; g < 4; g++)
#pragma unroll
        for (int m = 0; m < 4; m++)
#pragma unroll
            for (int s = 0; s < 4; s++) acc[g][m][s] = 0.f;

    const char* xsb = (const char*)xs;
    const char* wb  = (const char*)wsm;
#pragma unroll
    for (int kc = 0; kc < 8; kc++) {
        uint2 va[4], vb[4];
#pragma unroll
        for (int m = 0; m < 4; m++) {
            va[m] = *(const uint2*)(xsb + (m * 16 + gid) * HRB + kc * 32 + tig * 8);
            vb[m] = *(const uint2*)(xsb + (m * 16 + 8 + gid) * HRB + kc * 32 + tig * 8);
        }
#pragma unroll
        for (int g = 0; g < 4; g++) {
            uint2 b = *(const uint2*)(wb + (g * 128 + warp * 8 + gid) * HRB
                                      + kc * 32 + tig * 8);
#pragma unroll
            for (int m = 0; m < 4; m++)
                mma16(acc[g][m], va[m].x, vb[m].x, va[m].y, vb[m].y, b.x, b.y);
        }
    }
#pragma unroll
    for (int m = 0; m < 4; m++) {
        int rA = base + m * 16 + gid, rB = rA + 8;
        bool vA = rA < NN, vB = rB < NN;
        size_t nA = (size_t)rA * 512, nB = (size_t)rB * 512;
#pragma unroll
        for (int g = 0; g < 4; g++) {
            int col = g * 128 + cb;
            float2 bb = *(const float2*)&g_bsum[col];
            if (vA) *(unsigned*)&g_P[nA + col] =
                        packbf2(acc[g][m][1] + bb.y, acc[g][m][0] + bb.x);
            if (vB) *(unsigned*)&g_P[nB + col] =
                        packbf2(acc[g][m][3] + bb.y, acc[g][m][2] + bb.x);
        }
    }
}

// ------- lstm: two independent 256-thread groups (R15) + t=0 GEMM peeled -------
__global__ void __launch_bounds__(512, 1) lstm_kernel(const int* __restrict__ nbr) {
    extern __shared__ char smraw[];
    __nv_bfloat16* wsm = (__nv_bfloat16*)smraw;       // 512 x BST
    char* hall = smraw + 512 * BST * 2;               // 2 groups x 2 parity x 32 x HRB
    int*  snbr = (int*)(hall + 4 * HG);               // 64 x 16

    int tid = threadIdx.x, lane = tid & 31, warp = tid >> 5;
    int grp = warp >> 3, gw = warp & 7;
    int gid = lane >> 2, tig = lane & 3;
    int base0 = blockIdx.x * 64;
    int gbase = base0 + grp * 32;

    // stage W_hh once (all 512 threads)
#pragma unroll
    for (int i = 0; i < 16; i++) {
        int idx = tid + i * 512;
        int n = idx >> 4, c = idx & 15;
        cpa16(wsm + n * BST + c * 8, g_WhhB + n * 128 + c * 8);
    }
    cpcommit();
#pragma unroll
    for (int i = 0; i < 2; i++) {
        int idx = tid + i * 512;
        int r = idx >> 4;
        snbr[idx] = (base0 + r < NN) ? nbr[(size_t)(base0 + r) * 16 + (idx & 15)] : 0;
    }
    asm volatile("cp.async.wait_group 0;");
    __syncthreads();

    char* hbuf = hall + grp * 2 * HG;
    const char* wbase = (const char*)wsm;
    int cb = gw * 16 + 2 * tig;             // per-gate column base; tt adds +8
    int bid = grp + 1;                      // named barrier id (1 or 2)

    float acc[4][2][2][4];                  // [gate][tt][m][frag]
    float cst[2][2][4];                     // [m][tt][frag]
#pragma unroll
    for (int m = 0; m < 2; m++)
#pragma unroll
        for (int tt = 0; tt < 2; tt++)
#pragma unroll
            for (int z = 0; z < 4; z++) cst[m][tt][z] = 0.f;

    auto gatherP = [&](int t) {
#pragma unroll
        for (int m = 0; m < 2; m++) {
            int r0 = grp * 32 + m * 16 + gid;
            const __nv_bfloat16* PA = g_P + (size_t)snbr[r0 * 16 + t] * 512;
            const __nv_bfloat16* PB = g_P + (size_t)snbr[(r0 + 8) * 16 + t] * 512;
#pragma unroll
            for (int g = 0; g < 4; g++)
#pragma unroll
                for (int tt = 0; tt < 2; tt++) {
                    unsigned ua = *(const unsigned*)(PA + g * 128 + cb + tt * 8);
                    unsigned ub = *(const unsigned*)(PB + g * 128 + cb + tt * 8);
                    acc[g][tt][m][0] = lo2f(ua); acc[g][tt][m][1] = hi2f(ua);
                    acc[g][tt][m][2] = lo2f(ub); acc[g][tt][m][3] = hi2f(ub);
                }
        }
    };

    auto cell = [&](int t, char* hn) {
#pragma unroll
        for (int m = 0; m < 2; m++)
#pragma unroll
            for (int tt = 0; tt < 2; tt++) {
                float hv[4];
#pragma unroll
                for (int z = 0; z < 4; z++) {
                    float iv = siga(acc[0][tt][m][z]);
                    float fv = siga(acc[1][tt][m][z]);
                    float gv = tanha(acc[2][tt][m][z]);
                    float ov = siga(acc[3][tt][m][z]);
                    float c = fv * cst[m][tt][z] + iv * gv;
                    cst[m][tt][z] = c;
                    hv[z] = ov * tanha(c);
                }
                int u0 = cb + tt * 8;
                if (t < 15) {
                    int phys = (u0 & ~15) | ((u0 & 6) << 1) | ((u0 & 8) >> 2);
                    *(unsigned*)(hn + (m * 16 + gid) * HRB + phys * 2)     = packbf2(hv[1], hv[0]);
                    *(unsigned*)(hn + (m * 16 + 8 + gid) * HRB + phys * 2) = packbf2(hv[3], hv[2]);
                } else {
                    int rA = gbase + m * 16 + gid, rB = rA + 8;
                    if (rA < NN) *(float2*)&g_Hn[(size_t)rA * 128 + u0] = make_float2(hv[0], hv[1]);
                    if (rB < NN) *(float2*)&g_Hn[(size_t)rB * 128 + u0] = make_float2(hv[2], hv[3]);
                }
            }
    };

    // t = 0 peeled: h0 = 0, gates = P only -> no GEMM, no h-buffer zeroing
    gatherP(0);
    cell(0, hbuf + 1 * HG);      // writes buf1 (= parity of t=1 reads)
    gatherP(1);
    asm volatile("bar.sync %0, 256;" :: "r"(bid) : "memory");

    for (int t = 1; t < 16; t++) {
        const char* hc = hbuf + (t & 1) * HG;
        char*       hn = hbuf + ((t + 1) & 1) * HG;

        // acc += h @ Whh^T  (bf16 m16n8k16; group covers 32 rows x 512 cols)
#pragma unroll
        for (int kc = 0; kc < 8; kc++) {
            uint2 va0 = *(const uint2*)(hc + (gid)      * HRB + kc * 32 + tig * 8);
            uint2 vb0 = *(const uint2*)(hc + (8 + gid)  * HRB + kc * 32 + tig * 8);
            uint2 va1 = *(const uint2*)(hc + (16 + gid) * HRB + kc * 32 + tig * 8);
            uint2 vb1 = *(const uint2*)(hc + (24 + gid) * HRB + kc * 32 + tig * 8);
#pragma unroll
            for (int g = 0; g < 4; g++)
#pragma unroll
                for (int tt = 0; tt < 2; tt++) {
                    uint2 b = *(const uint2*)(wbase + (g * 128 + gw * 16 + tt * 8 + gid) * HRB
                                              + kc * 32 + tig * 8);
                    mma16(acc[g][tt][0], va0.x, vb0.x, va0.y, vb0.y, b.x, b.y);
                    mma16(acc[g][tt][1], va1.x, vb1.x, va1.y, vb1.y, b.x, b.y);
                }
        }

        cell(t, hn);
        if (t < 15) gatherP(t + 1);
        asm volatile("bar.sync %0, 256;" :: "r"(bid) : "memory");   // per-group step barrier
    }
}

// ---------------- out: o = x@Wself^T + hN@Wneigh^T + b  (+ ReLU / sigmoid) ----------------
template<int HOUT, int ACT>
__global__ void __launch_bounds__(512, 1) out_kernel(const float* __restrict__ xext, int sel,
                                                     float* __restrict__ oext, int osel) {
    extern __shared__ float sm[];
    float* xs = sm;
    float* h2 = xs + 64 * HSZ;
    float* ws = h2 + 64 * HSZ;
    float* wn = ws + HOUT * WFT;
    const float* x = sel ? g_H : xext;
    float* o = osel ? oext : g_H;
    int tid = threadIdx.x, lane = tid & 31, warp = tid >> 5;
    int wr = warp >> 2, cg = warp & 3, gid = lane >> 2, tig = lane & 3;
    int base = blockIdx.x * 64;
    int rowA = wr * 16 + gid, rowB = rowA + 8;
    bool vA = base + rowA < NN, vB = base + rowB < NN;

#pragma unroll
    for (int i = 0; i < 4; i++) {
        int idx = tid + i * 512;
        int r = idx >> 5, c = idx & 31;
        if (base + r < NN) {
            cpa16(xs + r * HSZ + c * 4, x    + (size_t)(base + r) * 128 + c * 4);
            cpa16(h2 + r * HSZ + c * 4, g_Hn + (size_t)(base + r) * 128 + c * 4);
        }
    }
#pragma unroll
    for (int i = 0; i < HOUT * 32 / 512; i++) {
        int idx = tid + i * 512;
        int n = idx >> 5, c = idx & 31;
        cpa16(ws + n * WFT + c * 4, g_Wself  + n * 128 + c * 4);
        cpa16(wn + n * WFT + c * 4, g_Wneigh + n * 128 + c * 4);
    }
    cpcommit();
    asm volatile("cp.async.wait_group 0;");
    __syncthreads();

    constexpr int T = HOUT / 32;
    float acc[T][4];
#pragma unroll
    for (int tt = 0; tt < T; tt++)
#pragma unroll
        for (int s = 0; s < 4; s++) acc[tt][s] = 0.f;

#pragma unroll
    for (int p = 0; p < 2; p++) {
        const float* As = p ? h2 : xs;
        const float* W  = p ? wn : ws;
#pragma unroll
        for (int kc = 0; kc < 16; kc++) {
            int kk = kc * 8;
            unsigned a0 = tf32u(As[rowA * HSZ + kk + tig]);
            unsigned a1 = tf32u(As[rowB * HSZ + kk + tig]);
            unsigned a2 = tf32u(As[rowA * HSZ + kk + tig + 4]);
            unsigned a3 = tf32u(As[rowB * HSZ + kk + tig + 4]);
#pragma unroll
            for (int tt = 0; tt < T; tt++) {
                float2 b = *(const float2*)&W[(cg * (HOUT / 4) + tt * 8 + gid) * WFT
                                              + kk + 2 * tig];
                mma8(acc[tt], a0, a1, a2, a3, __float_as_uint(b.x), __float_as_uint(b.y));
            }
        }
    }
#pragma unroll
    for (int tt = 0; tt < T; tt++)
#pragma unroll
        for (int s = 0; s < 4; s++) {
            int u = cg * (HOUT / 4) + tt * 8 + 2 * tig + (s & 1);
            float v = acc[tt][s] + g_bout[u];
            v = ACT ? sigf(v) : fmaxf(v, 0.f);
            int row = (s < 2) ? rowA : rowB;
            bool vv = (s < 2) ? vA : vB;
            if (vv) o[(size_t)(base + row) * HOUT + u] = v;
        }
}

// ---------------- launch ----------------
extern "C" void kernel_launch(void* const* d_in, const int* in_sizes, int n_in,
                              void* d_out, int out_size) {
    const float* feats = (const float*)d_in[0];
    const int*   nbr   = (const int*)d_in[1];

    const int PSM  = (512 * BST + 64 * BST) * 2;                 // 165888
    const int LSM  = 512 * BST * 2 + 4 * HG + 64 * 16 * 4;       // 188416
    const int OSM1 = (2 * 64 * HSZ + 2 * 128 * WFT) * 4;         // 206848
    const int OSM2 = (2 * 64 * HSZ + 2 * 64 * WFT) * 4;          // 137216
    cudaFuncSetAttribute(proj_kernel,       cudaFuncAttributeMaxDynamicSharedMemorySize, PSM);
    cudaFuncSetAttribute(lstm_kernel,       cudaFuncAttributeMaxDynamicSharedMemorySize, LSM);
    cudaFuncSetAttribute(out_kernel<128,0>, cudaFuncAttributeMaxDynamicSharedMemorySize, OSM1);
    cudaFuncSetAttribute(out_kernel<64,1>,  cudaFuncAttributeMaxDynamicSharedMemorySize, OSM2);

    dim3 g(NBLK), b(512);

    // layer 1
    prep_kernel<<<256, 256>>>((const float*)d_in[2], (const float*)d_in[3],
                              (const float*)d_in[4], (const float*)d_in[5],
                              (const float*)d_in[6], (const float*)d_in[7],
                              (const float*)d_in[8], 128);
    proj_kernel<<<g, b, PSM>>>(feats, 0);
    lstm_kernel<<<g, b, LSM>>>(nbr);
    out_kernel<128, 0><<<g, b, OSM1>>>(feats, 0, nullptr, 0);

    // layer 2
    prep_kernel<<<256, 256>>>((const float*)d_in[9],  (const float*)d_in[10],
                              (const float*)d_in[11], (const float*)d_in[12],
                              (const float*)d_in[13], (const float*)d_in[14],
                              (const float*)d_in[15], 64);
    proj_kernel<<<g, b, PSM>>>(nullptr, 1);
    lstm_kernel<<<g, b, LSM>>>(nbr);
    out_kernel<64, 1><<<g, b, OSM2>>>(nullptr, 1, (float*)d_out, 1);
}